// round 3
// baseline (speedup 1.0000x reference)
#include <cuda_runtime.h>
#include <cuda_bf16.h>

// Deformable conv2d, 1 channel, K=3, zero padding, torchvision bilinear rule.
// input : (B, 512, 512) f32
// weight: (1, 1, 3, 3)  f32
// offset: (B, 18, 512, 512) f32, planar layout [k*2+{y,x}][h][w]
// out   : (B, 512, 512) f32
//
// Block = 4 output rows x 512 cols. The 7 input rows covering all fast-path
// taps are staged in shared memory; bilinear gathers become conflict-free LDS.
// L1tex then only carries the coalesced 151MB offset stream + stores.

#define HH 512
#define WW 512
#define HW (512 * 512)
#define TILE_H 4
#define SROWS (TILE_H + 3)           // rows r0-1 .. r0+TILE_H+1

__device__ __forceinline__ float bilin_slow(const float* __restrict__ inb,
                                            float y, float x,
                                            float y0f, float x0f)
{
    float ly = y - y0f;
    float lx = x - x0f;
    float hy = 1.0f - ly;
    float hx = 1.0f - lx;
    int y0 = (int)y0f;
    int x0 = (int)x0f;
    int y1 = y0 + 1;
    int x1 = x0 + 1;
    bool y0v = (y0 >= 0) && (y0 < HH);
    bool y1v = (y1 >= 0) && (y1 < HH);
    bool x0v = (x0 >= 0) && (x0 < WW);
    bool x1v = (x1 >= 0) && (x1 < WW);
    float v00 = (y0v && x0v) ? __ldg(&inb[y0 * WW + x0]) : 0.0f;
    float v01 = (y0v && x1v) ? __ldg(&inb[y0 * WW + x1]) : 0.0f;
    float v10 = (y1v && x0v) ? __ldg(&inb[y1 * WW + x0]) : 0.0f;
    float v11 = (y1v && x1v) ? __ldg(&inb[y1 * WW + x1]) : 0.0f;
    return fmaf(hy, fmaf(hx, v00, lx * v01),
                ly * fmaf(hx, v10, lx * v11));
}

__global__ __launch_bounds__(256) void DeformConv_90735479095316_kernel(
    const float* __restrict__ inp,
    const float* __restrict__ wgt,
    const float* __restrict__ off,
    float* __restrict__ out)
{
    __shared__ float s_in[SROWS * WW];

    const int tid  = threadIdx.x;
    const int tile = blockIdx.x;                 // 8 * (512/TILE_H) tiles
    const int b    = tile >> 7;                  // 128 tiles per image
    const int r0   = (tile & 127) * TILE_H;

    const float* __restrict__ inb = inp + b * HW;

    // ---- Stage input rows r0-1 .. r0+TILE_H+1 into smem (contiguous span) ----
    {
        const int gbase = (r0 - 1) * WW;         // may be negative (row -1)
        #pragma unroll
        for (int i = tid * 4; i < SROWS * WW; i += 256 * 4) {
            int g = gbase + i;                   // float4-aligned (gbase % 512 == 0)
            float4 v;
            if (g >= 0 && g < HW) {
                v = *(const float4*)(inb + g);
            } else {
                v = make_float4(0.f, 0.f, 0.f, 0.f);
            }
            *(float4*)(s_in + i) = v;
        }
    }
    __syncthreads();

    float wk[9];
    #pragma unroll
    for (int k = 0; k < 9; k++) wk[k] = __ldg(&wgt[k]);

    const float* __restrict__ offb = off + (size_t)b * 18 * HW;

    // Each thread: 8 pixels = 4 rows x cols {tid, tid+256}.
    // Warp lanes cover 32 consecutive w -> gathers + offset loads coalesced.
    #pragma unroll 2
    for (int px = 0; px < 2 * TILE_H; px++) {
        const int rr = px >> 1;                  // 0..3
        const int r  = r0 + rr;
        const int w  = tid + ((px & 1) << 8);    // tid or tid+256

        const float* __restrict__ offp = offb + r * WW + w;

        const float yb = (float)r;
        const float xb = (float)w;
        float acc = 0.0f;

        #pragma unroll
        for (int k = 0; k < 9; k++) {
            const float ky = (float)(k / 3 - 1);
            const float kx = (float)(k % 3 - 1);

            float oy = __ldg(&offp[(2 * k) * HW]);
            float ox = __ldg(&offp[(2 * k + 1) * HW]);

            float y = yb + ky + oy;
            float x = xb + kx + ox;

            float y0f = floorf(y);
            float x0f = floorf(x);
            int y0 = (int)y0f;
            int x0 = (int)x0f;

            float v;
            if ((unsigned)y0 < (HH - 1) && (unsigned)x0 < (WW - 1) &&
                y0 >= r0 - 1 && y0 <= r0 + TILE_H - 2 + 2) {
                // Fast path: 2x2 footprint inside image AND inside the smem tile.
                float ly = y - y0f;
                float lx = x - x0f;
                float hy = 1.0f - ly;
                float hx = 1.0f - lx;
                const float* __restrict__ p =
                    s_in + (y0 - (r0 - 1)) * WW + x0;
                float v00 = p[0];
                float v01 = p[1];
                float v10 = p[WW];
                float v11 = p[WW + 1];
                v = fmaf(hy, fmaf(hx, v00, lx * v01),
                         ly * fmaf(hx, v10, lx * v11));
            } else {
                // Slow path: exact per-corner zeroing from global memory.
                v = bilin_slow(inb, y, x, y0f, x0f);
            }

            acc = fmaf(wk[k], v, acc);
        }

        out[b * HW + r * WW + w] = acc;
    }
}

extern "C" void kernel_launch(void* const* d_in, const int* in_sizes, int n_in,
                              void* d_out, int out_size)
{
    const float* inp = (const float*)d_in[0];
    const float* wgt = (const float*)d_in[1];
    const float* off = (const float*)d_in[2];
    float* out = (float*)d_out;

    int nblocks = (out_size / HW) * (HH / TILE_H);   // B * 128
    DeformConv_90735479095316_kernel<<<nblocks, 256>>>(inp, wgt, off, out);
}